// round 1
// baseline (speedup 1.0000x reference)
#include <cuda_runtime.h>
#include <math.h>
#include <stdint.h>

#define B_   2
#define S_   1024
#define E_   2048
#define NH_  16
#define DH_  128
#define EPS_ 1e-6f
#define NEC  12          // e-chunks for gates GEMM split-K
#define ECH  512         // 6144 / 12

// -------- device scratch (no allocations allowed) --------
__device__ float g_part[2 * NEC * B_ * NH_ * S_];   // gate partial sums (3 MB)
__device__ float g_a [B_ * NH_ * S_];               // a[j] = ig[j] - cum[j]
__device__ float g_rm[B_ * NH_ * S_];               // prefix max of a
__device__ float g_nl[B_ * NH_ * S_];               // exp(-(cum+rm)) = exp(-max_log_D)

// =====================================================================
// Kernel 1: gate partial GEMM.  grid (32 row-tiles, 12 e-chunks), 256 thr
// =====================================================================
__global__ __launch_bounds__(256, 1) void gates_partial_k(
    const float* __restrict__ q, const float* __restrict__ k,
    const float* __restrict__ v,
    const float* __restrict__ Wi, const float* __restrict__ Wf)
{
    __shared__ float Xs[64 * 65];
    __shared__ float Ws[64 * 32];
    const int rt = blockIdx.x;          // 0..31
    const int ec = blockIdx.y;          // 0..11
    const int b  = rt >> 4;
    const int s0 = (rt & 15) << 6;
    const int t  = threadIdx.x;
    const int rgrp = t & 15;            // rows rgrp*4 .. +3
    const int hgrp = t >> 4;            // heads hgrp*2, hgrp*2+1

    float acc[4][2] = {};

    for (int sub = 0; sub < 8; ++sub) {
        const int e0 = ec * ECH + sub * 64;
        const float* xp = (e0 < E_) ? q : (e0 < 2 * E_) ? k : v;
        const int col0 = e0 & (E_ - 1);
        __syncthreads();
        // stage x tile (64 rows x 64 e), coalesced
        for (int i = t; i < 64 * 64; i += 256) {
            int r = i >> 6, ee = i & 63;
            Xs[r * 65 + ee] = xp[((size_t)(b * S_ + s0 + r)) * E_ + col0 + ee];
        }
        // stage W tile (64 e x 32 heads): [Wi | Wf]
        for (int i = t; i < 64 * 32; i += 256) {
            int ee = i >> 5, hh = i & 31;
            int eg = e0 + ee;
            Ws[ee * 32 + hh] = (hh < 16) ? Wi[eg * 16 + hh] : Wf[eg * 16 + (hh - 16)];
        }
        __syncthreads();
        #pragma unroll 8
        for (int ee = 0; ee < 64; ++ee) {
            float xv[4];
            #pragma unroll
            for (int m = 0; m < 4; ++m) xv[m] = Xs[(rgrp * 4 + m) * 65 + ee];
            float wv0 = Ws[ee * 32 + hgrp * 2];
            float wv1 = Ws[ee * 32 + hgrp * 2 + 1];
            #pragma unroll
            for (int m = 0; m < 4; ++m) {
                acc[m][0] += xv[m] * wv0;
                acc[m][1] += xv[m] * wv1;
            }
        }
    }
    // write partials: layout [(gate*NEC+ec)][b*NH+h][s]
    #pragma unroll
    for (int m = 0; m < 4; ++m) {
        int s = s0 + rgrp * 4 + m;
        #pragma unroll
        for (int hh = 0; hh < 2; ++hh) {
            int hcol = hgrp * 2 + hh;
            int gate = hcol >> 4;
            int hm   = hcol & 15;
            g_part[((gate * NEC + ec) * (B_ * NH_) + b * NH_ + hm) * S_ + s] = acc[m][hh];
        }
    }
}

// =====================================================================
// Kernel 2: reduce partials + logsigmoid + inclusive scans (sum, max)
// grid 32 = (b,h), 1024 threads
// =====================================================================
__global__ __launch_bounds__(1024, 1) void scan_k(
    const float* __restrict__ bi, const float* __restrict__ bf)
{
    __shared__ float buf[1024];
    const int bh = blockIdx.x;
    const int t  = threadIdx.x;
    const int h  = bh & 15;

    float ig = bi[h], fg = bf[h];
    #pragma unroll
    for (int ec = 0; ec < NEC; ++ec) {
        ig += g_part[((0 * NEC + ec) * (B_ * NH_) + bh) * S_ + t];
        fg += g_part[((1 * NEC + ec) * (B_ * NH_) + bh) * S_ + t];
    }
    // log_sigmoid
    float lf = fminf(fg, 0.f) - log1pf(expf(-fabsf(fg)));

    // inclusive scan (sum) -> cum
    float x = lf;
    buf[t] = x; __syncthreads();
    for (int off = 1; off < 1024; off <<= 1) {
        float y = (t >= off) ? buf[t - off] : 0.f;
        __syncthreads();
        x += y; buf[t] = x; __syncthreads();
    }
    float cum = x;
    float a = ig - cum;

    // inclusive scan (max) -> rm
    x = a;
    buf[t] = x; __syncthreads();
    for (int off = 1; off < 1024; off <<= 1) {
        float y = (t >= off) ? buf[t - off] : -3.4e38f;
        __syncthreads();
        x = fmaxf(x, y); buf[t] = x; __syncthreads();
    }
    float rm = x;

    g_a [bh * S_ + t] = a;
    g_rm[bh * S_ + t] = rm;
    g_nl[bh * S_ + t] = expf(-(cum + rm));
}

// =====================================================================
// Kernel 3: causal mLSTM attention, 64x64 fp32 tiles + fused norm/LN
// grid (32 heads, 16 row-tiles), 256 threads, ~114KB dynamic smem
// =====================================================================
#define QLD 129
#define SLD 65
#define SM_FLOATS (64*QLD*2 + 64*128 + 64*SLD + 256)

__global__ __launch_bounds__(256, 1) void attn_k(
    const float* __restrict__ q, const float* __restrict__ k,
    const float* __restrict__ v, const float* __restrict__ lnsc,
    float* __restrict__ out)
{
    extern __shared__ float sm[];
    float* Qs  = sm;                 // 64 x (128 pad 129)
    float* Ks  = Qs + 64 * QLD;
    float* Vs  = Ks + 64 * QLD;      // 64 x 128 (float4 reads)
    float* Ss  = Vs + 64 * 128;      // 64 x (64 pad 65)
    float* aS  = Ss + 64 * SLD;
    float* rmS = aS + 64;
    float* nlS = rmS + 64;
    float* Cs  = nlS + 64;

    const int bh = blockIdx.x;
    const int b  = bh >> 4, h = bh & 15;
    const int ri = (int)gridDim.y - 1 - (int)blockIdx.y;  // big tiles first
    const int i0 = ri << 6;
    const int t  = threadIdx.x;
    const float scale = 0.08838834764831845f;  // 1/sqrt(128)

    // load Q tile + per-row stats
    {
        size_t baseq = ((size_t)(b * S_ + i0)) * E_ + h * DH_;
        for (int i = t; i < 64 * DH_; i += 256) {
            int r = i >> 7, d = i & 127;
            Qs[r * QLD + d] = q[baseq + (size_t)r * E_ + d];
        }
        if (t < 64) {
            rmS[t] = g_rm[bh * S_ + i0 + t];
            nlS[t] = g_nl[bh * S_ + i0 + t];
            Cs[t]  = 0.f;
        }
    }

    float acc[8][4] = {};
    const int w  = t >> 5, l  = t & 31;   // AV/output mapping
    const int rg = t >> 4, cg = t & 15;   // score mapping

    for (int jt = 0; jt <= ri; ++jt) {
        const int j0 = jt << 6;
        __syncthreads();   // previous AV readers done
        {
            size_t basek = ((size_t)(b * S_ + j0)) * E_ + h * DH_;
            for (int i = t; i < 64 * DH_; i += 256) {
                int r = i >> 7, d = i & 127;
                Ks[r * QLD + d] = k[basek + (size_t)r * E_ + d];
                Vs[r * 128 + d] = v[basek + (size_t)r * E_ + d];
            }
            if (t < 64) aS[t] = g_a[bh * S_ + j0 + t];
        }
        __syncthreads();

        // ---- scores: 4x4 per thread over 64x64 tile ----
        float sacc[4][4] = {};
        #pragma unroll 4
        for (int kk = 0; kk < DH_; ++kk) {
            float qv[4], kv[4];
            #pragma unroll
            for (int m = 0; m < 4; ++m) qv[m] = Qs[(rg * 4 + m) * QLD + kk];
            #pragma unroll
            for (int n = 0; n < 4; ++n) kv[n] = Ks[(cg * 4 + n) * QLD + kk];
            #pragma unroll
            for (int m = 0; m < 4; ++m)
                #pragma unroll
                for (int n = 0; n < 4; ++n)
                    sacc[m][n] += qv[m] * kv[n];
        }
        #pragma unroll
        for (int m = 0; m < 4; ++m) {
            const int r = rg * 4 + m;
            const int iglob = i0 + r;
            float rsum = 0.f;
            #pragma unroll
            for (int n = 0; n < 4; ++n) {
                const int c = cg * 4 + n;
                const int jglob = j0 + c;
                float p = (jglob <= iglob) ? expf(aS[c] - rmS[r]) : 0.f;
                float cval = sacc[m][n] * scale * p;
                Ss[r * SLD + c] = cval;
                rsum += cval;
            }
            // reduce rsum over the 16 cg threads (contiguous half-warp)
            #pragma unroll
            for (int off = 8; off > 0; off >>= 1)
                rsum += __shfl_down_sync(0xffffffffu, rsum, off, 16);
            if (cg == 0) Cs[r] += rsum;
        }
        __syncthreads();   // Ss ready

        // ---- AV: acc[8 rows][4 d] per thread ----
        #pragma unroll 2
        for (int j = 0; j < 64; ++j) {
            float4 vv = *(const float4*)(Vs + j * 128 + l * 4);
            #pragma unroll
            for (int rr = 0; rr < 8; ++rr) {
                float sv = Ss[(w * 8 + rr) * SLD + j];
                acc[rr][0] += sv * vv.x;
                acc[rr][1] += sv * vv.y;
                acc[rr][2] += sv * vv.z;
                acc[rr][3] += sv * vv.w;
            }
        }
    }
    __syncthreads();

    // ---- epilogue: normalizer + per-head LayerNorm + store ----
    const int dbase = l * 4;
    float ln0 = lnsc[h * DH_ + dbase + 0];
    float ln1 = lnsc[h * DH_ + dbase + 1];
    float ln2 = lnsc[h * DH_ + dbase + 2];
    float ln3 = lnsc[h * DH_ + dbase + 3];
    #pragma unroll
    for (int rr = 0; rr < 8; ++rr) {
        const int r = w * 8 + rr;
        float denom = fmaxf(fabsf(Cs[r]), nlS[r]) + EPS_;
        float inv = 1.f / denom;
        float hv[4];
        float s = 0.f;
        #pragma unroll
        for (int dd = 0; dd < 4; ++dd) { hv[dd] = acc[rr][dd] * inv; s += hv[dd]; }
        #pragma unroll
        for (int off = 16; off > 0; off >>= 1) s += __shfl_xor_sync(0xffffffffu, s, off);
        float mu = s * (1.f / 128.f);
        float vs = 0.f;
        #pragma unroll
        for (int dd = 0; dd < 4; ++dd) { float d0 = hv[dd] - mu; vs += d0 * d0; }
        #pragma unroll
        for (int off = 16; off > 0; off >>= 1) vs += __shfl_xor_sync(0xffffffffu, vs, off);
        float rstd = rsqrtf(vs * (1.f / 128.f) + EPS_);
        float4 o;
        o.x = (hv[0] - mu) * rstd * ln0;
        o.y = (hv[1] - mu) * rstd * ln1;
        o.z = (hv[2] - mu) * rstd * ln2;
        o.w = (hv[3] - mu) * rstd * ln3;
        *(float4*)(out + ((size_t)(b * S_ + i0 + r)) * E_ + h * DH_ + dbase) = o;
    }
}

// =====================================================================
extern "C" void kernel_launch(void* const* d_in, const int* in_sizes, int n_in,
                              void* d_out, int out_size)
{
    const float* q  = (const float*)d_in[0];
    const float* k  = (const float*)d_in[1];
    const float* v  = (const float*)d_in[2];
    const float* Wi = (const float*)d_in[3];
    const float* bi = (const float*)d_in[4];
    const float* Wf = (const float*)d_in[5];
    const float* bf = (const float*)d_in[6];
    const float* ln = (const float*)d_in[7];
    float* out = (float*)d_out;

    cudaFuncSetAttribute(attn_k, cudaFuncAttributeMaxDynamicSharedMemorySize,
                         SM_FLOATS * (int)sizeof(float));

    gates_partial_k<<<dim3(32, NEC), 256>>>(q, k, v, Wi, Wf);
    scan_k<<<B_ * NH_, 1024>>>(bi, bf);
    attn_k<<<dim3(B_ * NH_, 16), 256, SM_FLOATS * sizeof(float)>>>(q, k, v, ln, out);
}

// round 2
// speedup vs baseline: 1.2245x; 1.2245x over previous
#include <cuda_runtime.h>
#include <math.h>
#include <stdint.h>

#define B_   2
#define S_   1024
#define E_   2048
#define NH_  16
#define DH_  128
#define EPS_ 1e-6f
#define NEC  12          // e-chunks for gates GEMM split-K
#define ECH  512         // 6144 / 12

// ---------------- f32x2 helpers (Blackwell packed fp32) ----------------
#define FMA2(d, a, b)  asm("fma.rn.f32x2 %0, %1, %2, %0;" : "+l"(d) : "l"(a), "l"(b))
#define PACK2(d, x)    asm("mov.b64 %0, {%1, %1};" : "=l"(d) : "f"(x))

__device__ __forceinline__ void cpa16(uint32_t dst, const void* src) {
    asm volatile("cp.async.ca.shared.global [%0], [%1], 16;" :: "r"(dst), "l"(src));
}
__device__ __forceinline__ void cpa8(uint32_t dst, const void* src) {
    asm volatile("cp.async.ca.shared.global [%0], [%1], 8;" :: "r"(dst), "l"(src));
}
__device__ __forceinline__ void cpa_commit() { asm volatile("cp.async.commit_group;"); }

// -------- device scratch (no allocations allowed) --------
__device__ float g_part[2 * NEC * B_ * NH_ * S_];   // gate partial sums
__device__ float g_a [B_ * NH_ * S_];               // a[j] = ig[j] - cum[j]
__device__ float g_rm[B_ * NH_ * S_];               // prefix max of a
__device__ float g_nl[B_ * NH_ * S_];               // exp(-(cum+rm))

// =====================================================================
// Kernel 1: gate partial GEMM.  grid (32 row-tiles, 12 e-chunks), 256 thr
// per thread: 2 rows x 4 heads, f32x2 FMAs, float4 W reads
// =====================================================================
__global__ __launch_bounds__(256) void gates_partial_k(
    const float* __restrict__ q, const float* __restrict__ k,
    const float* __restrict__ v,
    const float* __restrict__ Wi, const float* __restrict__ Wf)
{
    __shared__ float Xs[64 * 65];
    __shared__ float Ws[64 * 32];
    const int rt = blockIdx.x;          // 0..31
    const int ec = blockIdx.y;          // 0..11
    const int b  = rt >> 4;
    const int s0 = (rt & 15) << 6;
    const int t  = threadIdx.x;
    const int rgrp = t >> 3;            // rows rgrp*2, rgrp*2+1
    const int hgrp = t & 7;             // heads hgrp*4 .. +3

    unsigned long long acc2[2][2] = {};

    for (int sub = 0; sub < 8; ++sub) {
        const int e0 = ec * ECH + sub * 64;
        const float* xp = (e0 < E_) ? q : (e0 < 2 * E_) ? k : v;
        const int col0 = e0 & (E_ - 1);
        __syncthreads();
        for (int i = t; i < 64 * 64; i += 256) {
            int r = i >> 6, ee = i & 63;
            Xs[r * 65 + ee] = xp[((size_t)(b * S_ + s0 + r)) * E_ + col0 + ee];
        }
        for (int i = t; i < 64 * 32; i += 256) {
            int ee = i >> 5, hh = i & 31;
            int eg = e0 + ee;
            Ws[ee * 32 + hh] = (hh < 16) ? Wi[eg * 16 + hh] : Wf[eg * 16 + (hh - 16)];
        }
        __syncthreads();
        #pragma unroll 8
        for (int ee = 0; ee < 64; ++ee) {
            unsigned long long xp2[2];
            #pragma unroll
            for (int m = 0; m < 2; ++m) {
                float xv = Xs[(rgrp * 2 + m) * 65 + ee];
                PACK2(xp2[m], xv);
            }
            ulonglong2 wv = *(const ulonglong2*)(Ws + ee * 32 + hgrp * 4);
            #pragma unroll
            for (int m = 0; m < 2; ++m) {
                FMA2(acc2[m][0], xp2[m], wv.x);
                FMA2(acc2[m][1], xp2[m], wv.y);
            }
        }
    }
    #pragma unroll
    for (int m = 0; m < 2; ++m) {
        int s = s0 + rgrp * 2 + m;
        #pragma unroll
        for (int p = 0; p < 2; ++p) {
            float2 u = *(float2*)&acc2[m][p];
            #pragma unroll
            for (int hh = 0; hh < 2; ++hh) {
                int hcol = hgrp * 4 + p * 2 + hh;
                int gate = hcol >> 4;
                int hm   = hcol & 15;
                float val = hh ? u.y : u.x;
                g_part[((gate * NEC + ec) * (B_ * NH_) + b * NH_ + hm) * S_ + s] = val;
            }
        }
    }
}

// =====================================================================
// Kernel 2: reduce partials + logsigmoid + inclusive scans (sum, max)
// =====================================================================
__global__ __launch_bounds__(1024, 1) void scan_k(
    const float* __restrict__ bi, const float* __restrict__ bf)
{
    __shared__ float buf[1024];
    const int bh = blockIdx.x;
    const int t  = threadIdx.x;
    const int h  = bh & 15;

    float ig = bi[h], fg = bf[h];
    #pragma unroll
    for (int ec = 0; ec < NEC; ++ec) {
        ig += g_part[((0 * NEC + ec) * (B_ * NH_) + bh) * S_ + t];
        fg += g_part[((1 * NEC + ec) * (B_ * NH_) + bh) * S_ + t];
    }
    float lf = fminf(fg, 0.f) - log1pf(expf(-fabsf(fg)));

    float x = lf;
    buf[t] = x; __syncthreads();
    for (int off = 1; off < 1024; off <<= 1) {
        float y = (t >= off) ? buf[t - off] : 0.f;
        __syncthreads();
        x += y; buf[t] = x; __syncthreads();
    }
    float cum = x;
    float a = ig - cum;

    x = a;
    buf[t] = x; __syncthreads();
    for (int off = 1; off < 1024; off <<= 1) {
        float y = (t >= off) ? buf[t - off] : -3.4e38f;
        __syncthreads();
        x = fmaxf(x, y); buf[t] = x; __syncthreads();
    }
    float rm = x;

    g_a [bh * S_ + t] = a;
    g_rm[bh * S_ + t] = rm;
    g_nl[bh * S_ + t] = expf(-(cum + rm));
}

// =====================================================================
// Kernel 3: causal mLSTM attention, 64x64 tiles, f32x2 + cp.async pipeline
// =====================================================================
#define QLD 130
#define SLD 66
#define SM_FLOATS (64*QLD + 2*64*QLD + 2*64*128 + 64*SLD + 2*64 + 64 + 64 + 64)

__global__ __launch_bounds__(256, 1) void attn_k(
    const float* __restrict__ q, const float* __restrict__ k,
    const float* __restrict__ v, const float* __restrict__ lnsc,
    float* __restrict__ out)
{
    extern __shared__ float sm[];
    float* Qs  = sm;                       // 64 x 130
    float* Ks  = Qs + 64 * QLD;            // 2 x 64 x 130
    float* Vs  = Ks + 2 * 64 * QLD;        // 2 x 64 x 128
    float* Ss  = Vs + 2 * 64 * 128;        // 64 x 66
    float* aS  = Ss + 64 * SLD;            // 2 x 64
    float* rmS = aS + 2 * 64;
    float* nlS = rmS + 64;
    float* Cs  = nlS + 64;

    const int bh = blockIdx.x;
    const int b  = bh >> 4, h = bh & 15;
    const int ri = (int)gridDim.y - 1 - (int)blockIdx.y;  // big tiles first
    const int i0 = ri << 6;
    const int t  = threadIdx.x;
    const float scale = 0.08838834764831845f;  // 1/sqrt(128)

    // ---- load Q tile (float2, stride 130) + per-row stats ----
    {
        size_t baseq = ((size_t)(b * S_ + i0)) * E_ + h * DH_;
        for (int i = t; i < 64 * 64; i += 256) {
            int r = i >> 6, d2 = (i & 63) * 2;
            *(float2*)(Qs + r * QLD + d2) = *(const float2*)(q + baseq + (size_t)r * E_ + d2);
        }
        if (t < 64) {
            rmS[t] = g_rm[bh * S_ + i0 + t];
            nlS[t] = g_nl[bh * S_ + i0 + t];
            Cs[t]  = 0.f;
        }
    }

    // ---- prefetch helper (inlined by macro-ish lambda) ----
    auto prefetch = [&](int buf, int j0) {
        float* Kb = Ks + buf * 64 * QLD;
        float* Vb = Vs + buf * 64 * 128;
        const float* kbase = k + ((size_t)(b * S_ + j0)) * E_ + h * DH_;
        const float* vbase = v + ((size_t)(b * S_ + j0)) * E_ + h * DH_;
        // V: 64x128 floats as 16B chunks
        #pragma unroll
        for (int c = 0; c < 8; ++c) {
            int idx = t + c * 256;
            int r = idx >> 5, d4 = (idx & 31) * 4;
            cpa16((uint32_t)__cvta_generic_to_shared(Vb + r * 128 + d4),
                  vbase + (size_t)r * E_ + d4);
        }
        // K: 64x128 floats as 8B chunks (stride 130)
        #pragma unroll
        for (int c = 0; c < 16; ++c) {
            int idx = t + c * 256;
            int r = idx >> 6, d2 = (idx & 63) * 2;
            cpa8((uint32_t)__cvta_generic_to_shared(Kb + r * QLD + d2),
                 kbase + (size_t)r * E_ + d2);
        }
        if (t < 16)
            cpa16((uint32_t)__cvta_generic_to_shared(aS + buf * 64 + t * 4),
                  g_a + bh * S_ + j0 + t * 4);
        cpa_commit();
    };

    prefetch(0, 0);

    unsigned long long acc2[8][2] = {};           // AV accumulators (d pairs)
    const int w  = t >> 5, l  = t & 31;           // AV/output mapping
    const int rg = t >> 4, cg = t & 15;           // score mapping (rows rg+16m, cols cg+16n)

    for (int jt = 0; jt <= ri; ++jt) {
        const int j0 = jt << 6;
        const int buf = jt & 1;
        if (jt < ri) {
            prefetch(buf ^ 1, j0 + 64);
            asm volatile("cp.async.wait_group 1;");
        } else {
            asm volatile("cp.async.wait_group 0;");
        }
        __syncthreads();   // K/V/a ready; prev AV readers done

        const float* Kb = Ks + buf * 64 * QLD;
        const float* ab = aS + buf * 64;

        // ---- scores: rows rg+16m, cols cg+16n, f32x2 along kk ----
        unsigned long long s2[4][4] = {};
        #pragma unroll 4
        for (int kk = 0; kk < DH_; kk += 2) {
            unsigned long long qv2[4], kv2[4];
            #pragma unroll
            for (int m = 0; m < 4; ++m)
                qv2[m] = *(const unsigned long long*)(Qs + (rg + 16 * m) * QLD + kk);
            #pragma unroll
            for (int n = 0; n < 4; ++n)
                kv2[n] = *(const unsigned long long*)(Kb + (cg + 16 * n) * QLD + kk);
            #pragma unroll
            for (int m = 0; m < 4; ++m)
                #pragma unroll
                for (int n = 0; n < 4; ++n)
                    FMA2(s2[m][n], qv2[m], kv2[n]);
        }
        #pragma unroll
        for (int m = 0; m < 4; ++m) {
            const int r = rg + 16 * m;
            const int iglob = i0 + r;
            float rsum = 0.f;
            #pragma unroll
            for (int n = 0; n < 4; ++n) {
                const int c = cg + 16 * n;
                const int jglob = j0 + c;
                float2 u = *(float2*)&s2[m][n];
                float sacc = u.x + u.y;
                float p = (jglob <= iglob) ? __expf(ab[c] - rmS[r]) : 0.f;
                float cval = sacc * scale * p;
                Ss[r * SLD + c] = cval;
                rsum += cval;
            }
            #pragma unroll
            for (int off = 8; off > 0; off >>= 1)
                rsum += __shfl_down_sync(0xffffffffu, rsum, off, 16);
            if (cg == 0) Cs[r] += rsum;
        }
        __syncthreads();   // Ss ready

        // ---- AV: acc[8 rows][4 d] per thread, f32x2 along d ----
        const float* Vb = Vs + buf * 64 * 128;
        #pragma unroll 2
        for (int j = 0; j < 64; ++j) {
            ulonglong2 vv = *(const ulonglong2*)(Vb + j * 128 + l * 4);
            #pragma unroll
            for (int rr = 0; rr < 8; ++rr) {
                float sv = Ss[(w * 8 + rr) * SLD + j];
                unsigned long long svp;
                PACK2(svp, sv);
                FMA2(acc2[rr][0], svp, vv.x);
                FMA2(acc2[rr][1], svp, vv.y);
            }
        }
        __syncthreads();   // AV done; buffers/Ss free
    }

    // ---- epilogue: normalizer + per-head LayerNorm + store ----
    const int dbase = l * 4;
    float ln0 = lnsc[h * DH_ + dbase + 0];
    float ln1 = lnsc[h * DH_ + dbase + 1];
    float ln2 = lnsc[h * DH_ + dbase + 2];
    float ln3 = lnsc[h * DH_ + dbase + 3];
    #pragma unroll
    for (int rr = 0; rr < 8; ++rr) {
        const int r = w * 8 + rr;
        float denom = fmaxf(fabsf(Cs[r]), nlS[r]) + EPS_;
        float inv = 1.f / denom;
        float2 a0 = *(float2*)&acc2[rr][0];
        float2 a1 = *(float2*)&acc2[rr][1];
        float hv[4] = {a0.x * inv, a0.y * inv, a1.x * inv, a1.y * inv};
        float s = hv[0] + hv[1] + hv[2] + hv[3];
        #pragma unroll
        for (int off = 16; off > 0; off >>= 1) s += __shfl_xor_sync(0xffffffffu, s, off);
        float mu = s * (1.f / 128.f);
        float vs = 0.f;
        #pragma unroll
        for (int dd = 0; dd < 4; ++dd) { float d0 = hv[dd] - mu; vs += d0 * d0; }
        #pragma unroll
        for (int off = 16; off > 0; off >>= 1) vs += __shfl_xor_sync(0xffffffffu, vs, off);
        float rstd = rsqrtf(vs * (1.f / 128.f) + EPS_);
        float4 o;
        o.x = (hv[0] - mu) * rstd * ln0;
        o.y = (hv[1] - mu) * rstd * ln1;
        o.z = (hv[2] - mu) * rstd * ln2;
        o.w = (hv[3] - mu) * rstd * ln3;
        *(float4*)(out + ((size_t)(b * S_ + i0 + r)) * E_ + h * DH_ + dbase) = o;
    }
}

// =====================================================================
extern "C" void kernel_launch(void* const* d_in, const int* in_sizes, int n_in,
                              void* d_out, int out_size)
{
    const float* q  = (const float*)d_in[0];
    const float* k  = (const float*)d_in[1];
    const float* v  = (const float*)d_in[2];
    const float* Wi = (const float*)d_in[3];
    const float* bi = (const float*)d_in[4];
    const float* Wf = (const float*)d_in[5];
    const float* bf = (const float*)d_in[6];
    const float* ln = (const float*)d_in[7];
    float* out = (float*)d_out;

    cudaFuncSetAttribute(attn_k, cudaFuncAttributeMaxDynamicSharedMemorySize,
                         SM_FLOATS * (int)sizeof(float));

    gates_partial_k<<<dim3(32, NEC), 256>>>(q, k, v, Wi, Wf);
    scan_k<<<B_ * NH_, 1024>>>(bi, bf);
    attn_k<<<dim3(B_ * NH_, 16), 256, SM_FLOATS * sizeof(float)>>>(q, k, v, ln, out);
}